// round 1
// baseline (speedup 1.0000x reference)
#include <cuda_runtime.h>

// Problem constants
#define BATCH 16
#define LP    2048
#define LQ    2048
#define HID   1024

// GEMM tiling
#define BM 128
#define BN 128
#define BK 16

// Scratch (allocation-free: __device__ globals)
__device__ float g_transq[(size_t)BATCH * LQ * HID];   // 134 MB
__device__ float g_att   [(size_t)BATCH * LP * LQ];    // 268 MB
__device__ float g_attvec[(size_t)BATCH * LP * HID];   // 134 MB

// ---------------- f32x2 packed-FMA helpers (FFMA2, sm_10x) ----------------
__device__ __forceinline__ unsigned long long pack2(float lo, float hi) {
    unsigned long long r;
    asm("mov.b64 %0, {%1, %2};" : "=l"(r) : "f"(lo), "f"(hi));
    return r;
}
__device__ __forceinline__ unsigned long long fma2(unsigned long long a,
                                                   unsigned long long b,
                                                   unsigned long long c) {
    unsigned long long d;
    asm("fma.rn.f32x2 %0, %1, %2, %3;" : "=l"(d) : "l"(a), "l"(b), "l"(c));
    return d;
}
__device__ __forceinline__ float2 unpack2(unsigned long long v) {
    float2 f;
    asm("mov.b64 {%0, %1}, %2;" : "=f"(f.x), "=f"(f.y) : "l"(v));
    return f;
}

// ---------------------------------------------------------------------------
// Generic tiled SGEMM:
//   C[m,n] = sum_k A[m,k] * B'[.,.]   (+bias[n]) (+ReLU)
//   A is always row-major [M,K] (k contiguous).
//   BKM=true : B is [N,K] row-major (k contiguous)  -> C = A * B^T
//   BKM=false: B is [K,N] row-major (n contiguous)  -> C = A * B
// Batched via blockIdx.z with element strides sA/sB/sC.
// Requires M%128==0, N%128==0, K%16==0.
// ---------------------------------------------------------------------------
template <bool BKM, bool BIAS, bool RELU>
__global__ __launch_bounds__(256)
void sgemm_kernel(const float* __restrict__ A, const float* __restrict__ Bg,
                  const float* __restrict__ bias, float* __restrict__ C,
                  int M, int N, int K,
                  long long sA, long long sB, long long sC)
{
    A  += sA * (long long)blockIdx.z;
    Bg += sB * (long long)blockIdx.z;
    C  += sC * (long long)blockIdx.z;

    const int m0 = blockIdx.y * BM;
    const int n0 = blockIdx.x * BN;
    const int tid = threadIdx.x;

    __shared__ float As[2][BK][BM];
    __shared__ float Bs[2][BK][BN];

    // ---- global loader mapping ----
    // A: 256 threads load 128 rows x 16 k as 2 float4 each.
    const int a_row = tid >> 2;          // 0..63 (and +64)
    const int a_kv  = (tid & 3) << 2;    // 0,4,8,12
    const float* Aptr = A + (long long)(m0 + a_row) * K + a_kv;

    // B loaders
    int b_row, b_col;
    if (BKM) { b_row = tid >> 2; b_col = (tid & 3) << 2; }   // N-row, K-col
    else     { b_row = tid >> 5; b_col = (tid & 31) << 2; }  // K-row, N-col
    const float* Bptr;
    if (BKM) Bptr = Bg + (long long)(n0 + b_row) * K + b_col;
    else     Bptr = Bg + (long long)b_row * N + (n0 + b_col);

    // ---- compute fragment mapping ----
    const int tx = tid & 15;             // n direction
    const int ty = tid >> 4;             // m direction
    // thread columns: {n0+tx*4 .. +3} and {n0+64+tx*4 .. +3}
    // thread rows:    {m0+ty*4 .. +3} and {m0+64+ty*4 .. +3}

    unsigned long long acc[8][4];
    #pragma unroll
    for (int i = 0; i < 8; i++)
        #pragma unroll
        for (int j = 0; j < 4; j++) acc[i][j] = 0ULL;

    const int nk = K / BK;

    float4 aR0, aR1, bR0, bR1;

    // ---- prologue: tile 0 ----
    aR0 = *(const float4*)(Aptr);
    aR1 = *(const float4*)(Aptr + 64LL * K);
    if (BKM) {
        bR0 = *(const float4*)(Bptr);
        bR1 = *(const float4*)(Bptr + 64LL * K);
    } else {
        bR0 = *(const float4*)(Bptr);
        bR1 = *(const float4*)(Bptr + 8LL * N);
    }
    // store tile 0 (A transposed, B per layout)
    As[0][a_kv + 0][a_row] = aR0.x;  As[0][a_kv + 1][a_row] = aR0.y;
    As[0][a_kv + 2][a_row] = aR0.z;  As[0][a_kv + 3][a_row] = aR0.w;
    As[0][a_kv + 0][a_row + 64] = aR1.x;  As[0][a_kv + 1][a_row + 64] = aR1.y;
    As[0][a_kv + 2][a_row + 64] = aR1.z;  As[0][a_kv + 3][a_row + 64] = aR1.w;
    if (BKM) {
        Bs[0][b_col + 0][b_row] = bR0.x;  Bs[0][b_col + 1][b_row] = bR0.y;
        Bs[0][b_col + 2][b_row] = bR0.z;  Bs[0][b_col + 3][b_row] = bR0.w;
        Bs[0][b_col + 0][b_row + 64] = bR1.x;  Bs[0][b_col + 1][b_row + 64] = bR1.y;
        Bs[0][b_col + 2][b_row + 64] = bR1.z;  Bs[0][b_col + 3][b_row + 64] = bR1.w;
    } else {
        *(float4*)&Bs[0][b_row][b_col]     = bR0;
        *(float4*)&Bs[0][b_row + 8][b_col] = bR1;
    }
    __syncthreads();

    for (int kt = 0; kt < nk; kt++) {
        const int buf = kt & 1;
        const bool more = (kt + 1) < nk;
        if (more) {
            const long long ko = (long long)(kt + 1) * BK;
            aR0 = *(const float4*)(Aptr + ko);
            aR1 = *(const float4*)(Aptr + ko + 64LL * K);
            if (BKM) {
                bR0 = *(const float4*)(Bptr + ko);
                bR1 = *(const float4*)(Bptr + ko + 64LL * K);
            } else {
                bR0 = *(const float4*)(Bptr + ko * N);
                bR1 = *(const float4*)(Bptr + ko * N + 8LL * N);
            }
        }

        #pragma unroll
        for (int kk = 0; kk < BK; kk++) {
            float4 a0 = *(const float4*)&As[buf][kk][ty * 4];
            float4 a1 = *(const float4*)&As[buf][kk][64 + ty * 4];
            float4 b0 = *(const float4*)&Bs[buf][kk][tx * 4];
            float4 b1 = *(const float4*)&Bs[buf][kk][64 + tx * 4];
            unsigned long long b2[4];
            b2[0] = pack2(b0.x, b0.y);
            b2[1] = pack2(b0.z, b0.w);
            b2[2] = pack2(b1.x, b1.y);
            b2[3] = pack2(b1.z, b1.w);
            float av[8] = {a0.x, a0.y, a0.z, a0.w, a1.x, a1.y, a1.z, a1.w};
            #pragma unroll
            for (int i = 0; i < 8; i++) {
                unsigned long long a2 = pack2(av[i], av[i]);
                #pragma unroll
                for (int j = 0; j < 4; j++)
                    acc[i][j] = fma2(a2, b2[j], acc[i][j]);
            }
        }

        if (more) {
            const int nb = buf ^ 1;
            As[nb][a_kv + 0][a_row] = aR0.x;  As[nb][a_kv + 1][a_row] = aR0.y;
            As[nb][a_kv + 2][a_row] = aR0.z;  As[nb][a_kv + 3][a_row] = aR0.w;
            As[nb][a_kv + 0][a_row + 64] = aR1.x;  As[nb][a_kv + 1][a_row + 64] = aR1.y;
            As[nb][a_kv + 2][a_row + 64] = aR1.z;  As[nb][a_kv + 3][a_row + 64] = aR1.w;
            if (BKM) {
                Bs[nb][b_col + 0][b_row] = bR0.x;  Bs[nb][b_col + 1][b_row] = bR0.y;
                Bs[nb][b_col + 2][b_row] = bR0.z;  Bs[nb][b_col + 3][b_row] = bR0.w;
                Bs[nb][b_col + 0][b_row + 64] = bR1.x;  Bs[nb][b_col + 1][b_row + 64] = bR1.y;
                Bs[nb][b_col + 2][b_row + 64] = bR1.z;  Bs[nb][b_col + 3][b_row + 64] = bR1.w;
            } else {
                *(float4*)&Bs[nb][b_row][b_col]     = bR0;
                *(float4*)&Bs[nb][b_row + 8][b_col] = bR1;
            }
            __syncthreads();
        }
    }

    // ---- epilogue ----
    const int row0 = m0 + ty * 4;
    const int col0 = n0 + tx * 4;
    float4 bv0 = make_float4(0.f, 0.f, 0.f, 0.f);
    float4 bv1 = make_float4(0.f, 0.f, 0.f, 0.f);
    if (BIAS) {
        bv0 = *(const float4*)&bias[col0];
        bv1 = *(const float4*)&bias[col0 + 64];
    }
    #pragma unroll
    for (int i = 0; i < 8; i++) {
        const int r = (i < 4) ? (row0 + i) : (row0 + 64 + (i - 4));
        float2 p0 = unpack2(acc[i][0]);
        float2 p1 = unpack2(acc[i][1]);
        float2 p2 = unpack2(acc[i][2]);
        float2 p3 = unpack2(acc[i][3]);
        float4 o0 = make_float4(p0.x, p0.y, p1.x, p1.y);
        float4 o1 = make_float4(p2.x, p2.y, p3.x, p3.y);
        if (BIAS) {
            o0.x += bv0.x; o0.y += bv0.y; o0.z += bv0.z; o0.w += bv0.w;
            o1.x += bv1.x; o1.y += bv1.y; o1.z += bv1.z; o1.w += bv1.w;
        }
        if (RELU) {
            o0.x = fmaxf(o0.x, 0.f); o0.y = fmaxf(o0.y, 0.f);
            o0.z = fmaxf(o0.z, 0.f); o0.w = fmaxf(o0.w, 0.f);
            o1.x = fmaxf(o1.x, 0.f); o1.y = fmaxf(o1.y, 0.f);
            o1.z = fmaxf(o1.z, 0.f); o1.w = fmaxf(o1.w, 0.f);
        }
        *(float4*)&C[(long long)r * N + col0]      = o0;
        *(float4*)&C[(long long)r * N + col0 + 64] = o1;
    }
}

// ---------------------------------------------------------------------------
// Row softmax over length 2048 (one CTA of 256 threads per row).
// ---------------------------------------------------------------------------
__global__ __launch_bounds__(256)
void softmax_kernel(float* __restrict__ att)
{
    float* row = att + (long long)blockIdx.x * 2048;
    const int tid = threadIdx.x;
    const int wid = tid >> 5, lane = tid & 31;

    float v[8];
    float m = -3.4e38f;
    #pragma unroll
    for (int i = 0; i < 8; i++) { v[i] = row[tid + 256 * i]; m = fmaxf(m, v[i]); }
    #pragma unroll
    for (int o = 16; o > 0; o >>= 1) m = fmaxf(m, __shfl_xor_sync(0xffffffffu, m, o));

    __shared__ float red[8];
    __shared__ float sval;
    if (lane == 0) red[wid] = m;
    __syncthreads();
    if (tid == 0) {
        float t = red[0];
        #pragma unroll
        for (int w = 1; w < 8; w++) t = fmaxf(t, red[w]);
        sval = t;
    }
    __syncthreads();
    m = sval;

    float s = 0.f;
    #pragma unroll
    for (int i = 0; i < 8; i++) { v[i] = expf(v[i] - m); s += v[i]; }
    #pragma unroll
    for (int o = 16; o > 0; o >>= 1) s += __shfl_xor_sync(0xffffffffu, s, o);
    __syncthreads();   // everyone has read sval / red before reuse
    if (lane == 0) red[wid] = s;
    __syncthreads();
    if (tid == 0) {
        float t = 0.f;
        #pragma unroll
        for (int w = 0; w < 8; w++) t += red[w];
        sval = 1.0f / t;
    }
    __syncthreads();
    const float inv = sval;
    #pragma unroll
    for (int i = 0; i < 8; i++) row[tid + 256 * i] = v[i] * inv;
}

// ---------------------------------------------------------------------------
extern "C" void kernel_launch(void* const* d_in, const int* in_sizes, int n_in,
                              void* d_out, int out_size)
{
    const float* proj_p = (const float*)d_in[0];   // [B, LP, H]
    const float* proj_q = (const float*)d_in[1];   // [B, LQ, H]
    const float* W      = (const float*)d_in[2];   // [H, H] (out, in)
    const float* bias   = (const float*)d_in[3];   // [H]
    float* out = (float*)d_out;                    // [B, LP, H]

    float *transq, *att, *attvec;
    cudaGetSymbolAddress((void**)&transq, g_transq);
    cudaGetSymbolAddress((void**)&att,    g_att);
    cudaGetSymbolAddress((void**)&attvec, g_attvec);

    const dim3 blk(256);

    // 1) trans_q = proj_q @ W^T + b          [B*LQ, H]
    sgemm_kernel<true, true, false><<<dim3(HID / BN, (BATCH * LQ) / BM, 1), blk>>>(
        proj_q, W, bias, transq, BATCH * LQ, HID, HID, 0, 0, 0);

    // 2) att[b] = proj_p[b] @ trans_q[b]^T   [LP, LQ] per batch
    sgemm_kernel<true, false, false><<<dim3(LQ / BN, LP / BM, BATCH), blk>>>(
        proj_p, transq, nullptr, att, LP, LQ, HID,
        (long long)LP * HID, (long long)LQ * HID, (long long)LP * LQ);

    // 3) softmax over last dim
    softmax_kernel<<<BATCH * LP, 256>>>(att);

    // 4) attvec[b] = att[b] @ proj_q[b]      [LP, H] per batch (B is n-major)
    sgemm_kernel<false, false, false><<<dim3(HID / BN, LP / BM, BATCH), blk>>>(
        att, proj_q, nullptr, attvec, LP, HID, LQ,
        (long long)LP * LQ, (long long)LQ * HID, (long long)LP * HID);

    // 5) out = relu(attvec @ W^T + b)        [B*LP, H]
    sgemm_kernel<true, true, true><<<dim3(HID / BN, (BATCH * LP) / BM, 1), blk>>>(
        attvec, W, bias, out, BATCH * LP, HID, HID, 0, 0, 0);
}